// round 2
// baseline (speedup 1.0000x reference)
#include <cuda_runtime.h>
#include <cuda_bf16.h>
#include <math.h>

#define NN 50000
#define EE 600000
#define DD 128
#define HH 8
#define DH 16
#define INV_SCALE 0.25f   // 1/sqrt(16)

// ---------------- scratch (static device allocations; no cudaMalloc) ----------
__device__ float g_Q[(size_t)NN * DD];
__device__ float g_K[(size_t)NN * DD];
__device__ float g_V[(size_t)NN * DD];
__device__ float g_scores[(size_t)EE * HH];
__device__ float g_nodemax[NN];
__device__ float g_ssum[(size_t)NN * HH];
__device__ float g_acc[(size_t)NN * DD];
__device__ int   g_row[EE];
__device__ int   g_col[EE];
__device__ int   g_is64;   // 1 if edge_index is int64, 0 if int32

// ---------------- helpers -----------------------------------------------------
__device__ __forceinline__ void atomicMaxFloat(float* addr, float v) {
    if (v >= 0.0f) atomicMax((int*)addr, __float_as_int(v));
    else           atomicMin((unsigned int*)addr, __float_as_uint(v));
}

// ---------------- edge_index dtype detection ----------------------------------
// int64 little-endian values in [0, 50000): every odd 32-bit word is 0.
// int32: odd words are random node ids — all-zero probability ~ (1/5e4)^64.
__global__ void detect_kernel(const unsigned int* __restrict__ ei32) {
    unsigned int acc = 0;
#pragma unroll
    for (int i = 0; i < 64; i++) acc |= ei32[2 * i + 1];
    g_is64 = (acc == 0) ? 1 : 0;
}

// ---------------- decode edge_index into int32 row/col -------------------------
__global__ __launch_bounds__(256) void decode_kernel(const unsigned int* __restrict__ ei32) {
    int i = blockIdx.x * blockDim.x + threadIdx.x;
    if (i >= EE) return;
    if (g_is64) {
        g_row[i] = (int)ei32[2 * (size_t)i];
        g_col[i] = (int)ei32[2 * ((size_t)EE + i)];
    } else {
        g_row[i] = (int)ei32[i];
        g_col[i] = (int)ei32[(size_t)EE + i];
    }
}

// ---------------- init: node_max=-inf, ssum=0, acc=0 --------------------------
__global__ void init_kernel() {
    int i = blockIdx.x * blockDim.x + threadIdx.x;
    if (i < NN) g_nodemax[i] = -INFINITY;
    if (i < NN * HH) g_ssum[i] = 0.0f;
    if (i < NN * DD) g_acc[i] = 0.0f;
}

// ---------------- GEMM: C[M,128] = A[M,128] @ B[128,128] + bias ---------------
// 128x128 block tile, 256 threads, 8x8 register tile per thread.
__global__ __launch_bounds__(256) void gemm128(
    const float* __restrict__ A, const float* __restrict__ B,
    const float* __restrict__ bias, float* __restrict__ C, int M)
{
    __shared__ float As[16][128];   // As[k][row]  (transposed x tile)
    __shared__ float Bs[16][128];   // Bs[k][col]
    const int tid = threadIdx.x;
    const int block_row = blockIdx.x * 128;
    const int tc = (tid & 15) * 8;   // first of 8 cols
    const int tr = (tid >> 4) * 8;   // first of 8 rows

    float acc[8][8];
#pragma unroll
    for (int i = 0; i < 8; i++)
#pragma unroll
        for (int j = 0; j < 8; j++) acc[i][j] = 0.0f;

    for (int k0 = 0; k0 < 128; k0 += 16) {
        // A tile: 128 rows x 16 k, stored transposed. 2048 floats, 8/thread.
#pragma unroll
        for (int j = 0; j < 2; j++) {
            int f  = tid * 8 + j * 4;        // 0..2047, aligned 4
            int r  = f >> 4;
            int kk = f & 15;
            int gr = block_row + r;
            float4 a = (gr < M) ? *(const float4*)(A + (size_t)gr * 128 + k0 + kk)
                                : make_float4(0.f, 0.f, 0.f, 0.f);
            As[kk + 0][r] = a.x;
            As[kk + 1][r] = a.y;
            As[kk + 2][r] = a.z;
            As[kk + 3][r] = a.w;
        }
        // B tile: 16 k x 128 cols, direct copy. 512 float4, 2/thread.
#pragma unroll
        for (int j = 0; j < 2; j++) {
            int f  = tid + j * 256;          // float4 index 0..511
            int kk = f >> 5;                 // 32 float4 per row
            int c4 = f & 31;
            *(float4*)(&Bs[kk][c4 * 4]) =
                *(const float4*)(B + (size_t)(k0 + kk) * 128 + c4 * 4);
        }
        __syncthreads();

#pragma unroll
        for (int kk = 0; kk < 16; kk++) {
            float a[8], b[8];
            *(float4*)(a)     = *(float4*)(&As[kk][tr]);
            *(float4*)(a + 4) = *(float4*)(&As[kk][tr + 4]);
            *(float4*)(b)     = *(float4*)(&Bs[kk][tc]);
            *(float4*)(b + 4) = *(float4*)(&Bs[kk][tc + 4]);
#pragma unroll
            for (int i = 0; i < 8; i++)
#pragma unroll
                for (int j = 0; j < 8; j++)
                    acc[i][j] = fmaf(a[i], b[j], acc[i][j]);
        }
        __syncthreads();
    }

    // epilogue: + bias, store
#pragma unroll
    for (int i = 0; i < 8; i++) {
        int gr = block_row + tr + i;
        if (gr >= M) break;
#pragma unroll
        for (int j = 0; j < 8; j += 4) {
            float4 o;
            o.x = acc[i][j + 0] + bias[tc + j + 0];
            o.y = acc[i][j + 1] + bias[tc + j + 1];
            o.z = acc[i][j + 2] + bias[tc + j + 2];
            o.w = acc[i][j + 3] + bias[tc + j + 3];
            *(float4*)(C + (size_t)gr * 128 + tc + j) = o;
        }
    }
}

// ---------------- per-edge scores + node max ----------------------------------
// One warp per edge. Lane t loads 4 floats; head h = t/4 (16 elems = 4 lanes).
__global__ __launch_bounds__(256) void scores_kernel(const float* __restrict__ ea)
{
    int e = (blockIdx.x * blockDim.x + threadIdx.x) >> 5;
    if (e >= EE) return;
    int lane = threadIdx.x & 31;
    int row = g_row[e];
    int col = g_col[e];

    float4 q = ((const float4*)(g_Q + (size_t)row * 128))[lane];
    float4 k = ((const float4*)(g_K + (size_t)col * 128))[lane];
    float p = q.x * k.x + q.y * k.y + q.z * k.z + q.w * k.w;
    p += __shfl_xor_sync(0xFFFFFFFFu, p, 1);
    p += __shfl_xor_sync(0xFFFFFFFFu, p, 2);   // all 4 lanes of a head hold the dot

    float score = p * INV_SCALE + ea[e];

    // max over heads (across the 8 head groups)
    float m = score;
    m = fmaxf(m, __shfl_xor_sync(0xFFFFFFFFu, m, 4));
    m = fmaxf(m, __shfl_xor_sync(0xFFFFFFFFu, m, 8));
    m = fmaxf(m, __shfl_xor_sync(0xFFFFFFFFu, m, 16));
    if (lane == 0) atomicMaxFloat(&g_nodemax[row], m);

    if ((lane & 3) == 0) g_scores[(size_t)e * HH + (lane >> 2)] = score;
}

// ---------------- exp + segment sum -------------------------------------------
// One thread per (edge, head).
__global__ __launch_bounds__(256) void expsum_kernel()
{
    int idx = blockIdx.x * blockDim.x + threadIdx.x;
    if (idx >= EE * HH) return;
    int e = idx >> 3;
    int h = idx & 7;
    int row = g_row[e];
    float s = __expf(g_scores[idx] - g_nodemax[row]);
    g_scores[idx] = s;
    atomicAdd(&g_ssum[row * HH + h], s);
}

// ---------------- weighted aggregation (scatter) --------------------------------
// One warp per edge: acc[row] += attn[e,h] * V[col]
__global__ __launch_bounds__(256) void aggregate_kernel()
{
    int e = (blockIdx.x * blockDim.x + threadIdx.x) >> 5;
    if (e >= EE) return;
    int lane = threadIdx.x & 31;
    int row = g_row[e];
    int col = g_col[e];
    int h = lane >> 2;

    float sexp = g_scores[(size_t)e * HH + h];
    float ssum = g_ssum[row * HH + h];
    float attn = sexp / (ssum + 1e-8f);

    float4 v = ((const float4*)(g_V + (size_t)col * 128))[lane];
    float* dst = g_acc + (size_t)row * 128 + lane * 4;
    atomicAdd(dst + 0, attn * v.x);
    atomicAdd(dst + 1, attn * v.y);
    atomicAdd(dst + 2, attn * v.z);
    atomicAdd(dst + 3, attn * v.w);
}

// ---------------- launch -------------------------------------------------------
extern "C" void kernel_launch(void* const* d_in, const int* in_sizes, int n_in,
                              void* d_out, int out_size)
{
    const float*        x   = (const float*)d_in[0];
    const unsigned int* ei  = (const unsigned int*)d_in[1];
    const float*        ea  = (const float*)d_in[2];
    const float*        Wq  = (const float*)d_in[3];
    const float*        bq  = (const float*)d_in[4];
    const float*        Wk  = (const float*)d_in[5];
    const float*        bk  = (const float*)d_in[6];
    const float*        Wv  = (const float*)d_in[7];
    const float*        bv  = (const float*)d_in[8];
    const float*        Wo  = (const float*)d_in[9];
    const float*        bo  = (const float*)d_in[10];
    float*              out = (float*)d_out;

    float* dQ;   cudaGetSymbolAddress((void**)&dQ,   g_Q);
    float* dK;   cudaGetSymbolAddress((void**)&dK,   g_K);
    float* dV;   cudaGetSymbolAddress((void**)&dV,   g_V);
    float* dACC; cudaGetSymbolAddress((void**)&dACC, g_acc);

    // edge_index dtype detection + decode to int32 row/col
    detect_kernel<<<1, 1>>>(ei);
    decode_kernel<<<(EE + 255) / 256, 256>>>(ei);

    // init node_max / ssum / acc
    {
        int total = NN * DD;
        init_kernel<<<(total + 255) / 256, 256>>>();
    }

    // Q, K, V projections
    {
        int grid = (NN + 127) / 128;
        gemm128<<<grid, 256>>>(x, Wq, bq, dQ, NN);
        gemm128<<<grid, 256>>>(x, Wk, bk, dK, NN);
        gemm128<<<grid, 256>>>(x, Wv, bv, dV, NN);
    }

    // per-edge scores + node max  (8 edges / 256-thread block)
    scores_kernel<<<(EE + 7) / 8, 256>>>(ea);

    // exp + segment sum
    {
        int total = EE * HH;
        expsum_kernel<<<(total + 255) / 256, 256>>>();
    }

    // scatter-aggregate attn * V
    aggregate_kernel<<<(EE + 7) / 8, 256>>>();

    // output projection
    gemm128<<<(NN + 127) / 128, 256>>>(dACC, Wo, bo, out, NN);
}

// round 3
// speedup vs baseline: 1.3431x; 1.3431x over previous
#include <cuda_runtime.h>
#include <cuda_bf16.h>
#include <math.h>

#define NN 50000
#define EE 600000
#define DD 128
#define HH 8
#define DH 16
#define INV_SCALE 0.25f   // 1/sqrt(16)

// ---------------- scratch (static device allocations; no cudaMalloc) ----------
__device__ float g_Q[(size_t)NN * DD];
__device__ float g_K[(size_t)NN * DD];
__device__ float g_V[(size_t)NN * DD];
__device__ float g_scores[(size_t)EE * HH];
__device__ float g_nodemax[NN];
__device__ float g_ssum[(size_t)NN * HH];
__device__ float g_acc[(size_t)NN * DD];
__device__ int   g_row[EE];
__device__ int   g_col[EE];
__device__ int   g_is64;   // 1 if edge_index is int64, 0 if int32

// ---------------- helpers -----------------------------------------------------
__device__ __forceinline__ void atomicMaxFloat(float* addr, float v) {
    if (v >= 0.0f) atomicMax((int*)addr, __float_as_int(v));
    else           atomicMin((unsigned int*)addr, __float_as_uint(v));
}

__device__ __forceinline__ void redAddV4(float* addr, float a, float b, float c, float d) {
    asm volatile("red.global.add.v4.f32 [%0], {%1, %2, %3, %4};"
                 :: "l"(addr), "f"(a), "f"(b), "f"(c), "f"(d) : "memory");
}

// ---------------- edge_index dtype detection ----------------------------------
// int64 little-endian values in [0, 50000): every odd 32-bit word is 0.
// int32: odd words are random node ids — all-zero probability ~ (1/5e4)^64.
__global__ void detect_kernel(const unsigned int* __restrict__ ei32) {
    unsigned int acc = 0;
#pragma unroll
    for (int i = 0; i < 64; i++) acc |= ei32[2 * i + 1];
    g_is64 = (acc == 0) ? 1 : 0;
}

// ---------------- decode edge_index into int32 row/col -------------------------
__global__ __launch_bounds__(256) void decode_kernel(const unsigned int* __restrict__ ei32) {
    int i = blockIdx.x * blockDim.x + threadIdx.x;
    if (i >= EE) return;
    if (g_is64) {
        g_row[i] = (int)ei32[2 * (size_t)i];
        g_col[i] = (int)ei32[2 * ((size_t)EE + i)];
    } else {
        g_row[i] = (int)ei32[i];
        g_col[i] = (int)ei32[(size_t)EE + i];
    }
}

// ---------------- init: node_max=-inf, ssum=0, acc=0 --------------------------
__global__ void init_kernel() {
    int i = blockIdx.x * blockDim.x + threadIdx.x;
    if (i < NN) g_nodemax[i] = -INFINITY;
    if (i < NN * HH) g_ssum[i] = 0.0f;
    if (i < NN * DD) g_acc[i] = 0.0f;
}

// ---------------- GEMM core: C[M,128] = A[M,128] @ B[128,128] + bias ----------
// 128x128 block tile, 256 threads, 8x8 register tile per thread.
__device__ __forceinline__ void gemm128_body(
    const float* __restrict__ A, const float* __restrict__ B,
    const float* __restrict__ bias, float* __restrict__ C, int M)
{
    __shared__ float As[16][128];   // As[k][row]  (transposed A tile)
    __shared__ float Bs[16][128];   // Bs[k][col]
    const int tid = threadIdx.x;
    const int block_row = blockIdx.x * 128;
    const int tc = (tid & 15) * 8;   // first of 8 cols
    const int tr = (tid >> 4) * 8;   // first of 8 rows

    float acc[8][8];
#pragma unroll
    for (int i = 0; i < 8; i++)
#pragma unroll
        for (int j = 0; j < 8; j++) acc[i][j] = 0.0f;

    for (int k0 = 0; k0 < 128; k0 += 16) {
#pragma unroll
        for (int j = 0; j < 2; j++) {
            int f  = tid * 8 + j * 4;        // 0..2047, aligned 4
            int r  = f >> 4;
            int kk = f & 15;
            int gr = block_row + r;
            float4 a = (gr < M) ? *(const float4*)(A + (size_t)gr * 128 + k0 + kk)
                                : make_float4(0.f, 0.f, 0.f, 0.f);
            As[kk + 0][r] = a.x;
            As[kk + 1][r] = a.y;
            As[kk + 2][r] = a.z;
            As[kk + 3][r] = a.w;
        }
#pragma unroll
        for (int j = 0; j < 2; j++) {
            int f  = tid + j * 256;          // float4 index 0..511
            int kk = f >> 5;
            int c4 = f & 31;
            *(float4*)(&Bs[kk][c4 * 4]) =
                *(const float4*)(B + (size_t)(k0 + kk) * 128 + c4 * 4);
        }
        __syncthreads();

#pragma unroll
        for (int kk = 0; kk < 16; kk++) {
            float a[8], b[8];
            *(float4*)(a)     = *(float4*)(&As[kk][tr]);
            *(float4*)(a + 4) = *(float4*)(&As[kk][tr + 4]);
            *(float4*)(b)     = *(float4*)(&Bs[kk][tc]);
            *(float4*)(b + 4) = *(float4*)(&Bs[kk][tc + 4]);
#pragma unroll
            for (int i = 0; i < 8; i++)
#pragma unroll
                for (int j = 0; j < 8; j++)
                    acc[i][j] = fmaf(a[i], b[j], acc[i][j]);
        }
        __syncthreads();
    }

#pragma unroll
    for (int i = 0; i < 8; i++) {
        int gr = block_row + tr + i;
        if (gr >= M) break;
#pragma unroll
        for (int j = 0; j < 8; j += 4) {
            float4 o;
            o.x = acc[i][j + 0] + bias[tc + j + 0];
            o.y = acc[i][j + 1] + bias[tc + j + 1];
            o.z = acc[i][j + 2] + bias[tc + j + 2];
            o.w = acc[i][j + 3] + bias[tc + j + 3];
            *(float4*)(C + (size_t)gr * 128 + tc + j) = o;
        }
    }
}

// fused QKV: blockIdx.y selects (W, b, C)
__global__ __launch_bounds__(256) void gemm_qkv(
    const float* __restrict__ A,
    const float* __restrict__ Wq, const float* __restrict__ bq,
    const float* __restrict__ Wk, const float* __restrict__ bk,
    const float* __restrict__ Wv, const float* __restrict__ bv,
    int M)
{
    const float* B;
    const float* bias;
    float* C;
    if (blockIdx.y == 0)      { B = Wq; bias = bq; C = g_Q; }
    else if (blockIdx.y == 1) { B = Wk; bias = bk; C = g_K; }
    else                      { B = Wv; bias = bv; C = g_V; }
    gemm128_body(A, B, bias, C, M);
}

__global__ __launch_bounds__(256) void gemm_single(
    const float* __restrict__ A, const float* __restrict__ B,
    const float* __restrict__ bias, float* __restrict__ C, int M)
{
    gemm128_body(A, B, bias, C, M);
}

// ---------------- per-edge scores + node max ----------------------------------
// One warp per edge. Lane t loads 4 floats; head h = t/4 (16 elems = 4 lanes).
__global__ __launch_bounds__(256) void scores_kernel(const float* __restrict__ ea)
{
    int e = (blockIdx.x * blockDim.x + threadIdx.x) >> 5;
    if (e >= EE) return;
    int lane = threadIdx.x & 31;
    int row = g_row[e];
    int col = g_col[e];

    float4 q = ((const float4*)(g_Q + (size_t)row * 128))[lane];
    float4 k = ((const float4*)(g_K + (size_t)col * 128))[lane];
    float p = q.x * k.x + q.y * k.y + q.z * k.z + q.w * k.w;
    p += __shfl_xor_sync(0xFFFFFFFFu, p, 1);
    p += __shfl_xor_sync(0xFFFFFFFFu, p, 2);   // all 4 lanes of a head hold the dot

    float score = p * INV_SCALE + ea[e];

    // max over heads
    float m = score;
    m = fmaxf(m, __shfl_xor_sync(0xFFFFFFFFu, m, 4));
    m = fmaxf(m, __shfl_xor_sync(0xFFFFFFFFu, m, 8));
    m = fmaxf(m, __shfl_xor_sync(0xFFFFFFFFu, m, 16));
    if (lane == 0) atomicMaxFloat(&g_nodemax[row], m);

    if ((lane & 3) == 0) g_scores[(size_t)e * HH + (lane >> 2)] = score;
}

// ---------------- fused exp + segment-sum + weighted scatter -------------------
// One warp per edge: s = exp(score - max[row]); ssum[row,h] += s;
// acc[row] += s * V[col]   (division by ssum deferred to normalize pass)
__global__ __launch_bounds__(256) void aggregate_kernel()
{
    int e = (blockIdx.x * blockDim.x + threadIdx.x) >> 5;
    if (e >= EE) return;
    int lane = threadIdx.x & 31;
    int row = g_row[e];
    int col = g_col[e];

    float s = 0.0f;
    if (lane < 8) {
        float sc = g_scores[(size_t)e * HH + lane];
        s = __expf(sc - g_nodemax[row]);
        atomicAdd(&g_ssum[row * HH + lane], s);   // no return use -> RED
    }
    float w = __shfl_sync(0xFFFFFFFFu, s, lane >> 2);

    float4 v = ((const float4*)(g_V + (size_t)col * 128))[lane];
    redAddV4(g_acc + (size_t)row * 128 + lane * 4,
             w * v.x, w * v.y, w * v.z, w * v.w);
}

// ---------------- normalize: acc /= (ssum + 1e-8) -------------------------------
// one float4 per thread: NN*32 float4s
__global__ __launch_bounds__(256) void normalize_kernel()
{
    int idx = blockIdx.x * blockDim.x + threadIdx.x;
    if (idx >= NN * 32) return;
    int n = idx >> 5;
    int q = idx & 31;          // float4 index within row; head = q>>2
    float inv = 1.0f / (g_ssum[n * HH + (q >> 2)] + 1e-8f);
    float4* p = (float4*)(g_acc + (size_t)n * 128 + q * 4);
    float4 v = *p;
    v.x *= inv; v.y *= inv; v.z *= inv; v.w *= inv;
    *p = v;
}

// ---------------- launch -------------------------------------------------------
extern "C" void kernel_launch(void* const* d_in, const int* in_sizes, int n_in,
                              void* d_out, int out_size)
{
    const float*        x   = (const float*)d_in[0];
    const unsigned int* ei  = (const unsigned int*)d_in[1];
    const float*        ea  = (const float*)d_in[2];
    const float*        Wq  = (const float*)d_in[3];
    const float*        bq  = (const float*)d_in[4];
    const float*        Wk  = (const float*)d_in[5];
    const float*        bk  = (const float*)d_in[6];
    const float*        Wv  = (const float*)d_in[7];
    const float*        bv  = (const float*)d_in[8];
    const float*        Wo  = (const float*)d_in[9];
    const float*        bo  = (const float*)d_in[10];
    float*              out = (float*)d_out;

    float* dACC; cudaGetSymbolAddress((void**)&dACC, g_acc);

    // edge_index dtype detection + decode to int32 row/col
    detect_kernel<<<1, 1>>>(ei);
    decode_kernel<<<(EE + 255) / 256, 256>>>(ei);

    // init node_max / ssum / acc
    init_kernel<<<(NN * DD + 255) / 256, 256>>>();

    // fused Q,K,V projections (one launch -> minimal wave quantization)
    {
        dim3 grid((NN + 127) / 128, 3);
        gemm_qkv<<<grid, 256>>>(x, Wq, bq, Wk, bk, Wv, bv, NN);
    }

    // per-edge scores + node max  (8 edges / 256-thread block)
    scores_kernel<<<(EE + 7) / 8, 256>>>(ea);

    // fused exp + segment-sum + scatter (unnormalized)
    aggregate_kernel<<<(EE + 7) / 8, 256>>>();

    // normalize acc by segment sums
    normalize_kernel<<<(NN * 32 + 255) / 256, 256>>>();

    // output projection
    gemm_single<<<(NN + 127) / 128, 256>>>(dACC, Wo, bo, out, NN);
}

// round 4
// speedup vs baseline: 1.7299x; 1.2880x over previous
#include <cuda_runtime.h>
#include <cuda_bf16.h>
#include <math.h>

#define NN 50000
#define EE 600000
#define DD 128
#define HH 8
#define DH 16
#define INV_SCALE 0.25f   // 1/sqrt(16)

// ---------------- scratch (static device allocations; no cudaMalloc) ----------
__device__ float g_Q[(size_t)NN * DD];
__device__ float g_K[(size_t)NN * DD];
__device__ float g_V[(size_t)NN * DD];
__device__ float g_ssum[(size_t)NN * HH];
__device__ float g_acc[(size_t)NN * DD];
__device__ int   g_row[EE];
__device__ int   g_col[EE];
__device__ int   g_is64;   // 1 if edge_index is int64, 0 if int32

// ---------------- helpers -----------------------------------------------------
__device__ __forceinline__ void redAddV4(float* addr, float a, float b, float c, float d) {
    asm volatile("red.global.add.v4.f32 [%0], {%1, %2, %3, %4};"
                 :: "l"(addr), "f"(a), "f"(b), "f"(c), "f"(d) : "memory");
}

// ---------------- edge_index dtype detection ----------------------------------
// int64 little-endian values in [0, 50000): every odd 32-bit word is 0.
// int32: odd words are random node ids — all-zero probability ~ (1/5e4)^64.
__global__ void detect_kernel(const unsigned int* __restrict__ ei32) {
    unsigned int acc = 0;
#pragma unroll
    for (int i = 0; i < 64; i++) acc |= ei32[2 * i + 1];
    g_is64 = (acc == 0) ? 1 : 0;
}

// ---------------- decode edge_index into int32 row/col -------------------------
__global__ __launch_bounds__(256) void decode_kernel(const unsigned int* __restrict__ ei32) {
    int i = blockIdx.x * blockDim.x + threadIdx.x;
    if (i >= EE) return;
    if (g_is64) {
        g_row[i] = (int)ei32[2 * (size_t)i];
        g_col[i] = (int)ei32[2 * ((size_t)EE + i)];
    } else {
        g_row[i] = (int)ei32[i];
        g_col[i] = (int)ei32[(size_t)EE + i];
    }
}

// ---------------- init: ssum=0, acc=0 ------------------------------------------
__global__ void init_kernel() {
    int i = blockIdx.x * blockDim.x + threadIdx.x;
    if (i < NN * HH) g_ssum[i] = 0.0f;
    if (i < NN * DD) g_acc[i] = 0.0f;
}

// ---------------- GEMM core: C[M,128] = A[M,128] @ B[128,128] + bias ----------
// 128x128 block tile, 256 threads, 8x8 register tile per thread.
// If NORM, A rows are scaled per-head by 1/(ssum[row,head]+1e-8) during load
// (k-tile [k0,k0+16) is exactly one head).
template <bool NORM>
__device__ __forceinline__ void gemm128_body(
    const float* __restrict__ A, const float* __restrict__ B,
    const float* __restrict__ bias, float* __restrict__ C, int M)
{
    __shared__ float As[16][128];   // As[k][row]  (transposed A tile)
    __shared__ float Bs[16][128];   // Bs[k][col]
    const int tid = threadIdx.x;
    const int block_row = blockIdx.x * 128;
    const int tc = (tid & 15) * 8;   // first of 8 cols
    const int tr = (tid >> 4) * 8;   // first of 8 rows

    float acc[8][8];
#pragma unroll
    for (int i = 0; i < 8; i++)
#pragma unroll
        for (int j = 0; j < 8; j++) acc[i][j] = 0.0f;

    for (int k0 = 0; k0 < 128; k0 += 16) {
        const int head = k0 >> 4;
#pragma unroll
        for (int j = 0; j < 2; j++) {
            int f  = tid * 8 + j * 4;        // 0..2047, aligned 4
            int r  = f >> 4;
            int kk = f & 15;
            int gr = block_row + r;
            float4 a = (gr < M) ? *(const float4*)(A + (size_t)gr * 128 + k0 + kk)
                                : make_float4(0.f, 0.f, 0.f, 0.f);
            if (NORM && gr < M) {
                float inv = 1.0f / (g_ssum[gr * HH + head] + 1e-8f);
                a.x *= inv; a.y *= inv; a.z *= inv; a.w *= inv;
            }
            As[kk + 0][r] = a.x;
            As[kk + 1][r] = a.y;
            As[kk + 2][r] = a.z;
            As[kk + 3][r] = a.w;
        }
#pragma unroll
        for (int j = 0; j < 2; j++) {
            int f  = tid + j * 256;          // float4 index 0..511
            int kk = f >> 5;
            int c4 = f & 31;
            *(float4*)(&Bs[kk][c4 * 4]) =
                *(const float4*)(B + (size_t)(k0 + kk) * 128 + c4 * 4);
        }
        __syncthreads();

#pragma unroll
        for (int kk = 0; kk < 16; kk++) {
            float a[8], b[8];
            *(float4*)(a)     = *(float4*)(&As[kk][tr]);
            *(float4*)(a + 4) = *(float4*)(&As[kk][tr + 4]);
            *(float4*)(b)     = *(float4*)(&Bs[kk][tc]);
            *(float4*)(b + 4) = *(float4*)(&Bs[kk][tc + 4]);
#pragma unroll
            for (int i = 0; i < 8; i++)
#pragma unroll
                for (int j = 0; j < 8; j++)
                    acc[i][j] = fmaf(a[i], b[j], acc[i][j]);
        }
        __syncthreads();
    }

#pragma unroll
    for (int i = 0; i < 8; i++) {
        int gr = block_row + tr + i;
        if (gr >= M) break;
#pragma unroll
        for (int j = 0; j < 8; j += 4) {
            float4 o;
            o.x = acc[i][j + 0] + bias[tc + j + 0];
            o.y = acc[i][j + 1] + bias[tc + j + 1];
            o.z = acc[i][j + 2] + bias[tc + j + 2];
            o.w = acc[i][j + 3] + bias[tc + j + 3];
            *(float4*)(C + (size_t)gr * 128 + tc + j) = o;
        }
    }
}

// fused QKV: blockIdx.y selects (W, b, C)
__global__ __launch_bounds__(256) void gemm_qkv(
    const float* __restrict__ A,
    const float* __restrict__ Wq, const float* __restrict__ bq,
    const float* __restrict__ Wk, const float* __restrict__ bk,
    const float* __restrict__ Wv, const float* __restrict__ bv,
    int M)
{
    const float* B;
    const float* bias;
    float* C;
    if (blockIdx.y == 0)      { B = Wq; bias = bq; C = g_Q; }
    else if (blockIdx.y == 1) { B = Wk; bias = bk; C = g_K; }
    else                      { B = Wv; bias = bv; C = g_V; }
    gemm128_body<false>(A, B, bias, C, M);
}

// final GEMM with fused softmax normalization of A
__global__ __launch_bounds__(256) void gemm_out(
    const float* __restrict__ A, const float* __restrict__ B,
    const float* __restrict__ bias, float* __restrict__ C, int M)
{
    gemm128_body<true>(A, B, bias, C, M);
}

// ---------------- fused edge pass ----------------------------------------------
// One warp per edge. Lane t: head h = t>>2.
//   s_h = exp(qk_h/4 + ea[e]);  ssum[row,h] += s_h;  acc[row] += s_h * V[col]
// (softmax shift-invariance: max subtraction dropped; scores bounded ~±6)
__global__ __launch_bounds__(256) void edge_kernel(const float* __restrict__ ea)
{
    int e = (blockIdx.x * blockDim.x + threadIdx.x) >> 5;
    if (e >= EE) return;
    int lane = threadIdx.x & 31;
    int row = g_row[e];
    int col = g_col[e];

    float4 q = ((const float4*)(g_Q + (size_t)row * 128))[lane];
    float4 k = ((const float4*)(g_K + (size_t)col * 128))[lane];
    float p = q.x * k.x + q.y * k.y + q.z * k.z + q.w * k.w;
    p += __shfl_xor_sync(0xFFFFFFFFu, p, 1);
    p += __shfl_xor_sync(0xFFFFFFFFu, p, 2);   // all 4 lanes of head h hold dot_h

    float s = __expf(fmaf(p, INV_SCALE, ea[e]));   // this lane's head weight

    if ((lane & 3) == 0) atomicAdd(&g_ssum[row * HH + (lane >> 2)], s);

    float4 v = ((const float4*)(g_V + (size_t)col * 128))[lane];
    redAddV4(g_acc + (size_t)row * 128 + lane * 4,
             s * v.x, s * v.y, s * v.z, s * v.w);
}

// ---------------- launch -------------------------------------------------------
extern "C" void kernel_launch(void* const* d_in, const int* in_sizes, int n_in,
                              void* d_out, int out_size)
{
    const float*        x   = (const float*)d_in[0];
    const unsigned int* ei  = (const unsigned int*)d_in[1];
    const float*        ea  = (const float*)d_in[2];
    const float*        Wq  = (const float*)d_in[3];
    const float*        bq  = (const float*)d_in[4];
    const float*        Wk  = (const float*)d_in[5];
    const float*        bk  = (const float*)d_in[6];
    const float*        Wv  = (const float*)d_in[7];
    const float*        bv  = (const float*)d_in[8];
    const float*        Wo  = (const float*)d_in[9];
    const float*        bo  = (const float*)d_in[10];
    float*              out = (float*)d_out;

    float* dACC; cudaGetSymbolAddress((void**)&dACC, g_acc);

    // edge_index dtype detection + decode to int32 row/col
    detect_kernel<<<1, 1>>>(ei);
    decode_kernel<<<(EE + 255) / 256, 256>>>(ei);

    // init ssum / acc
    init_kernel<<<(NN * DD + 255) / 256, 256>>>();

    // fused Q,K,V projections
    {
        dim3 grid((NN + 127) / 128, 3);
        gemm_qkv<<<grid, 256>>>(x, Wq, bq, Wk, bk, Wv, bv, NN);
    }

    // fused scores + exp + segment-sum + scatter (8 edges / 256-thread block)
    edge_kernel<<<(EE + 7) / 8, 256>>>(ea);

    // output projection with fused normalization
    gemm_out<<<(NN + 127) / 128, 256>>>(dACC, Wo, bo, out, NN);
}

// round 6
// speedup vs baseline: 2.0940x; 1.2105x over previous
#include <cuda_runtime.h>
#include <cuda_bf16.h>
#include <math.h>
#include <stdint.h>

#define NN 50000
#define EE 600000
#define DD 128
#define HH 8
#define INV_SCALE 0.25f   // 1/sqrt(16)

// ---------------- scratch (static device allocations; no cudaMalloc) ----------
__device__ float g_Q[(size_t)NN * DD];
__device__ float g_K[(size_t)NN * DD];
__device__ float g_V[(size_t)NN * DD];
__device__ float g_ssum[(size_t)NN * HH];
__device__ float g_acc[(size_t)NN * DD];
__device__ int   g_row[EE];
__device__ int   g_col[EE];
__device__ int   g_is64;
// pre-transposed weights, split hi/lo bf16, stored N x K row-major:
// g_B[mat][part][n*128 + k] = part(W[k][n])
__device__ __align__(16) __nv_bfloat16 g_B[4][2][128 * 128];

// ---------------- helpers -------------------------------------------------------
__device__ __forceinline__ uint32_t smem_u32(const void* p) {
    uint32_t a;
    asm("{ .reg .u64 t; cvta.to.shared.u64 t, %1; cvt.u32.u64 %0, t; }" : "=r"(a) : "l"(p));
    return a;
}
__device__ __forceinline__ void redAddV4(float* addr, float a, float b, float c, float d) {
    asm volatile("red.global.add.v4.f32 [%0], {%1, %2, %3, %4};"
                 :: "l"(addr), "f"(a), "f"(b), "f"(c), "f"(d) : "memory");
}
__device__ __forceinline__ uint32_t pack_bf16(float x, float y) {
    __nv_bfloat162 t = __floats2bfloat162_rn(x, y);   // low = x, high = y
    return *(uint32_t*)&t;
}
__device__ __forceinline__ float bf16_round(float x) {
    return __bfloat162float(__float2bfloat16_rn(x));
}
__device__ __forceinline__ void ldmatrix_x4(uint32_t& r0, uint32_t& r1,
                                            uint32_t& r2, uint32_t& r3, uint32_t addr) {
    asm volatile("ldmatrix.sync.aligned.m8n8.x4.shared.b16 {%0,%1,%2,%3}, [%4];"
                 : "=r"(r0), "=r"(r1), "=r"(r2), "=r"(r3) : "r"(addr));
}
__device__ __forceinline__ void mma_bf16(float* c, const uint32_t* a, const uint32_t* b) {
    asm volatile(
        "mma.sync.aligned.m16n8k16.row.col.f32.bf16.bf16.f32 "
        "{%0,%1,%2,%3}, {%4,%5,%6,%7}, {%8,%9}, {%0,%1,%2,%3};"
        : "+f"(c[0]), "+f"(c[1]), "+f"(c[2]), "+f"(c[3])
        : "r"(a[0]), "r"(a[1]), "r"(a[2]), "r"(a[3]), "r"(b[0]), "r"(b[1]));
}

// ---------------- edge_index dtype detection + decode ---------------------------
__global__ void detect_kernel(const unsigned int* __restrict__ ei32) {
    unsigned int acc = 0;
#pragma unroll
    for (int i = 0; i < 64; i++) acc |= ei32[2 * i + 1];
    g_is64 = (acc == 0) ? 1 : 0;
}
__global__ __launch_bounds__(256) void decode_kernel(const unsigned int* __restrict__ ei32) {
    int i = blockIdx.x * blockDim.x + threadIdx.x;
    if (i >= EE) return;
    if (g_is64) {
        g_row[i] = (int)ei32[2 * (size_t)i];
        g_col[i] = (int)ei32[2 * ((size_t)EE + i)];
    } else {
        g_row[i] = (int)ei32[i];
        g_col[i] = (int)ei32[(size_t)EE + i];
    }
}

// ---------------- init: ssum=0, acc=0 -------------------------------------------
__global__ void init_kernel() {
    int i = blockIdx.x * blockDim.x + threadIdx.x;
    if (i < NN * HH) g_ssum[i] = 0.0f;
    if (i < NN * DD) g_acc[i] = 0.0f;
}

// ---------------- weight prep: transpose + hi/lo split ---------------------------
__global__ __launch_bounds__(256) void prep_kernel(
    const float* __restrict__ Wq, const float* __restrict__ Wk,
    const float* __restrict__ Wv, const float* __restrict__ Wo)
{
    int m = blockIdx.y;
    const float* src = (m == 0) ? Wq : (m == 1) ? Wk : (m == 2) ? Wv : Wo;
    int idx = blockIdx.x * 256 + threadIdx.x;   // 0..16383
    int n = idx >> 7, k = idx & 127;
    float v = src[k * 128 + n];
    __nv_bfloat16 h = __float2bfloat16_rn(v);
    __nv_bfloat16 l = __float2bfloat16_rn(v - __bfloat162float(h));
    g_B[m][0][n * 128 + k] = h;
    g_B[m][1][n * 128 + k] = l;
}

// ---------------- tensor-core GEMM (split bf16, 3-product fp32 restore) ---------
// C[M,128] = A[M,128] @ W + bias.  B = g_B[mat] (N x K hi/lo planes).
// If NORM: A rows pre-scaled per-head by 1/(ssum[row][head]+1e-8).
// SMEM: sA hi/lo planes 128x136 bf16 each, then sB hi/lo planes 128x136.
#define PS      (128 * 136)          // plane elems
#define PSB     (PS * 2)             // plane bytes
#define SB_OFF  (2 * PSB)            // sB byte offset
#define SMEM_GEMM (4 * PSB)          // 139264 bytes

template <bool NORM>
__device__ __forceinline__ void gemm_mma_body(
    const float* __restrict__ A, const __nv_bfloat16* __restrict__ Bsrc,
    const float* __restrict__ bias, float* __restrict__ C, int M)
{
    extern __shared__ __nv_bfloat16 smem[];
    const uint32_t sb = smem_u32(smem);
    const int tid = threadIdx.x;
    const int lane = tid & 31;
    const int wid = tid >> 5;
    const int warp_m = wid >> 1;          // 0..3  -> 32 rows
    const int warp_n = wid & 1;           // 0..1  -> 64 cols
    const int block_row = blockIdx.x * 128;

    // ---- load B planes (hi then lo) into sB with stride 136 ----
    {
        const uint32_t* src = (const uint32_t*)Bsrc;       // 2 planes x 8192 u32
        uint32_t* dst = (uint32_t*)(smem + 2 * PS);
#pragma unroll
        for (int p = 0; p < 2; p++) {
#pragma unroll 8
            for (int i = tid; i < 8192; i += 256) {
                int row = i >> 6, colw = i & 63;
                dst[p * (PS / 2) + row * 68 + colw] = src[p * 8192 + i];
            }
        }
    }

    // ---- convert A tile fp32 -> hi/lo bf16 planes (stride 136) ----
    {
        int r = tid >> 1;                       // 0..127
        int half = tid & 1;                     // 64-col half
        int gr = block_row + r;
        uint32_t* hi = (uint32_t*)smem + (r * 136 + half * 64) / 2;
        uint32_t* lo = hi + PS / 2;
        if (gr < M) {
            const float4* Arow = (const float4*)(A + (size_t)gr * 128 + half * 64);
            float sc[4];
            if (NORM) {
#pragma unroll
                for (int h = 0; h < 4; h++)
                    sc[h] = 1.0f / (g_ssum[gr * 8 + half * 4 + h] + 1e-8f);
            }
#pragma unroll
            for (int i = 0; i < 16; i++) {
                float4 a = Arow[i];
                if (NORM) { float s = sc[i >> 2]; a.x *= s; a.y *= s; a.z *= s; a.w *= s; }
                hi[2 * i]     = pack_bf16(bf16_round(a.x), bf16_round(a.y));
                hi[2 * i + 1] = pack_bf16(bf16_round(a.z), bf16_round(a.w));
                lo[2 * i]     = pack_bf16(a.x - bf16_round(a.x), a.y - bf16_round(a.y));
                lo[2 * i + 1] = pack_bf16(a.z - bf16_round(a.z), a.w - bf16_round(a.w));
            }
        } else {
#pragma unroll
            for (int i = 0; i < 32; i++) { hi[i] = 0u; lo[i] = 0u; }
        }
    }
    __syncthreads();

    // ---- fragment addresses (bytes), stride 136 bf16 = 272 B ----
    // A (row-major M x K): x4 matrices [m0-7,k0-7][m8-15,k0-7][m0-7,k8-15][m8-15,k8-15]
    uint32_t aAddr[2];
#pragma unroll
    for (int mt = 0; mt < 2; mt++)
        aAddr[mt] = sb + ((warp_m * 32 + mt * 16 + (lane & 15)) * 136 +
                          ((lane >> 4) << 3)) * 2;
    // B (N x K rows=n): x4 covers 16 n-cols: [k0-7,n0-7][k8-15,n0-7][k0-7,n8-15][k8-15,n8-15]
    uint32_t bAddr[4];
#pragma unroll
    for (int g = 0; g < 4; g++)
        bAddr[g] = sb + SB_OFF +
                   ((warp_n * 64 + g * 16 + ((lane >> 4) << 3) + (lane & 7)) * 136 +
                    (((lane >> 3) & 1) << 3)) * 2;

    float c[2][8][4];
#pragma unroll
    for (int mt = 0; mt < 2; mt++)
#pragma unroll
        for (int nt = 0; nt < 8; nt++)
#pragma unroll
            for (int j = 0; j < 4; j++) c[mt][nt][j] = 0.0f;

    // ---- main loop: 3 passes (Ah*Bh, Ah*Bl, Al*Bh) x 8 k16-steps ----
#pragma unroll
    for (int pass = 0; pass < 3; pass++) {
        const uint32_t aOff = (pass == 2) ? PSB : 0u;
        const uint32_t bOff = (pass == 1) ? PSB : 0u;
#pragma unroll
        for (int k = 0; k < 8; k++) {
            const uint32_t kb = (uint32_t)k * 32;   // 16 bf16 = 32 B
            uint32_t a[2][4];
#pragma unroll
            for (int mt = 0; mt < 2; mt++)
                ldmatrix_x4(a[mt][0], a[mt][1], a[mt][2], a[mt][3],
                            aAddr[mt] + aOff + kb);
            uint32_t b[8][2];
#pragma unroll
            for (int g = 0; g < 4; g++) {
                uint32_t r0, r1, r2, r3;
                ldmatrix_x4(r0, r1, r2, r3, bAddr[g] + bOff + kb);
                b[2 * g][0] = r0; b[2 * g][1] = r1;
                b[2 * g + 1][0] = r2; b[2 * g + 1][1] = r3;
            }
#pragma unroll
            for (int mt = 0; mt < 2; mt++)
#pragma unroll
                for (int nt = 0; nt < 8; nt++)
                    mma_bf16(c[mt][nt], a[mt], b[nt]);
        }
    }

    // ---- epilogue: +bias, store ----
#pragma unroll
    for (int mt = 0; mt < 2; mt++) {
        int m0 = block_row + warp_m * 32 + mt * 16 + (lane >> 2);
#pragma unroll
        for (int nt = 0; nt < 8; nt++) {
            int n0 = warp_n * 64 + nt * 8 + (lane & 3) * 2;
            float bx = __ldg(bias + n0), by = __ldg(bias + n0 + 1);
            if (m0 < M) {
                float2 o = make_float2(c[mt][nt][0] + bx, c[mt][nt][1] + by);
                *(float2*)(C + (size_t)m0 * 128 + n0) = o;
            }
            if (m0 + 8 < M) {
                float2 o = make_float2(c[mt][nt][2] + bx, c[mt][nt][3] + by);
                *(float2*)(C + (size_t)(m0 + 8) * 128 + n0) = o;
            }
        }
    }
}

// QKV: blockIdx.y = mat
__global__ __launch_bounds__(256, 1) void gemm_qkv_mma(
    const float* __restrict__ x,
    const float* __restrict__ bq, const float* __restrict__ bk,
    const float* __restrict__ bv, int M)
{
    int m = blockIdx.y;
    const float* bias = (m == 0) ? bq : (m == 1) ? bk : bv;
    float* C = (m == 0) ? g_Q : (m == 1) ? g_K : g_V;
    gemm_mma_body<false>(x, &g_B[m][0][0], bias, C, M);
}

// output projection with fused softmax normalization
__global__ __launch_bounds__(256, 1) void gemm_out_mma(
    const float* __restrict__ bo, float* __restrict__ out, int M)
{
    gemm_mma_body<true>(g_acc, &g_B[3][0][0], bo, out, M);
}

// ---------------- fused edge pass ------------------------------------------------
__global__ __launch_bounds__(256) void edge_kernel(const float* __restrict__ ea)
{
    int e = (blockIdx.x * blockDim.x + threadIdx.x) >> 5;
    if (e >= EE) return;
    int lane = threadIdx.x & 31;
    int row = g_row[e];
    int col = g_col[e];

    float4 q = ((const float4*)(g_Q + (size_t)row * 128))[lane];
    float4 k = ((const float4*)(g_K + (size_t)col * 128))[lane];
    float p = q.x * k.x + q.y * k.y + q.z * k.z + q.w * k.w;
    p += __shfl_xor_sync(0xFFFFFFFFu, p, 1);
    p += __shfl_xor_sync(0xFFFFFFFFu, p, 2);   // all 4 lanes of head h hold dot_h

    float s = __expf(fmaf(p, INV_SCALE, ea[e]));

    if ((lane & 3) == 0) atomicAdd(&g_ssum[row * HH + (lane >> 2)], s);

    float4 v = ((const float4*)(g_V + (size_t)col * 128))[lane];
    redAddV4(g_acc + (size_t)row * 128 + lane * 4,
             s * v.x, s * v.y, s * v.z, s * v.w);
}

// ---------------- launch ----------------------------------------------------------
extern "C" void kernel_launch(void* const* d_in, const int* in_sizes, int n_in,
                              void* d_out, int out_size)
{
    const float*        x   = (const float*)d_in[0];
    const unsigned int* ei  = (const unsigned int*)d_in[1];
    const float*        ea  = (const float*)d_in[2];
    const float*        Wq  = (const float*)d_in[3];
    const float*        bq  = (const float*)d_in[4];
    const float*        Wk  = (const float*)d_in[5];
    const float*        bk  = (const float*)d_in[6];
    const float*        Wv  = (const float*)d_in[7];
    const float*        bv  = (const float*)d_in[8];
    const float*        Wo  = (const float*)d_in[9];
    const float*        bo  = (const float*)d_in[10];
    float*              out = (float*)d_out;

    cudaFuncSetAttribute(gemm_qkv_mma, cudaFuncAttributeMaxDynamicSharedMemorySize, SMEM_GEMM);
    cudaFuncSetAttribute(gemm_out_mma, cudaFuncAttributeMaxDynamicSharedMemorySize, SMEM_GEMM);

    // edge_index dtype detection + decode
    detect_kernel<<<1, 1>>>(ei);
    decode_kernel<<<(EE + 255) / 256, 256>>>(ei);

    // init ssum / acc
    init_kernel<<<(NN * DD + 255) / 256, 256>>>();

    // weight prep (transpose + hi/lo split)
    {
        dim3 grid(64, 4);
        prep_kernel<<<grid, 256>>>(Wq, Wk, Wv, Wo);
    }

    // fused Q,K,V projections on tensor cores
    {
        dim3 grid((NN + 127) / 128, 3);
        gemm_qkv_mma<<<grid, 256, SMEM_GEMM>>>(x, bq, bk, bv, NN);
    }

    // fused scores + exp + segment-sum + scatter
    edge_kernel<<<(EE + 7) / 8, 256>>>(ea);

    // output projection (normalization fused) on tensor cores
    gemm_out_mma<<<(NN + 127) / 128, 256, SMEM_GEMM>>>(bo, out, NN);
}

// round 7
// speedup vs baseline: 2.2031x; 1.0521x over previous
#include <cuda_runtime.h>
#include <cuda_bf16.h>
#include <cuda_fp16.h>
#include <math.h>
#include <stdint.h>

#define NN 50000
#define EE 600000
#define DD 128
#define HH 8
#define INV_SCALE 0.25f   // 1/sqrt(16)

// ---------------- scratch (static device allocations; no cudaMalloc) ----------
__device__ __half g_Qh[(size_t)NN * DD];
__device__ __half g_Kh[(size_t)NN * DD];
__device__ __half g_Vh[(size_t)NN * DD];
__device__ float  g_ssum[(size_t)NN * HH];
__device__ float  g_acc[(size_t)NN * DD];
__device__ int    g_row[EE];
__device__ int    g_col[EE];
__device__ int    g_is64;
// pre-transposed weights, split hi/lo bf16, stored N x K row-major
__device__ __align__(16) __nv_bfloat16 g_B[4][2][128 * 128];

// ---------------- helpers -------------------------------------------------------
__device__ __forceinline__ uint32_t smem_u32(const void* p) {
    uint32_t a;
    asm("{ .reg .u64 t; cvta.to.shared.u64 t, %1; cvt.u32.u64 %0, t; }" : "=r"(a) : "l"(p));
    return a;
}
__device__ __forceinline__ void redAddV4(float* addr, float a, float b, float c, float d) {
    asm volatile("red.global.add.v4.f32 [%0], {%1, %2, %3, %4};"
                 :: "l"(addr), "f"(a), "f"(b), "f"(c), "f"(d) : "memory");
}
__device__ __forceinline__ uint32_t pack_bf16(float x, float y) {
    __nv_bfloat162 t = __floats2bfloat162_rn(x, y);   // low = x, high = y
    return *(uint32_t*)&t;
}
__device__ __forceinline__ float bf16_round(float x) {
    return __bfloat162float(__float2bfloat16_rn(x));
}
__device__ __forceinline__ void ldmatrix_x4(uint32_t& r0, uint32_t& r1,
                                            uint32_t& r2, uint32_t& r3, uint32_t addr) {
    asm volatile("ldmatrix.sync.aligned.m8n8.x4.shared.b16 {%0,%1,%2,%3}, [%4];"
                 : "=r"(r0), "=r"(r1), "=r"(r2), "=r"(r3) : "r"(addr));
}
__device__ __forceinline__ void mma_bf16(float* c, const uint32_t* a, const uint32_t* b) {
    asm volatile(
        "mma.sync.aligned.m16n8k16.row.col.f32.bf16.bf16.f32 "
        "{%0,%1,%2,%3}, {%4,%5,%6,%7}, {%8,%9}, {%0,%1,%2,%3};"
        : "+f"(c[0]), "+f"(c[1]), "+f"(c[2]), "+f"(c[3])
        : "r"(a[0]), "r"(a[1]), "r"(a[2]), "r"(a[3]), "r"(b[0]), "r"(b[1]));
}

// ---------------- edge_index dtype detection + decode ---------------------------
__global__ void detect_kernel(const unsigned int* __restrict__ ei32) {
    unsigned int acc = 0;
#pragma unroll
    for (int i = 0; i < 64; i++) acc |= ei32[2 * i + 1];
    g_is64 = (acc == 0) ? 1 : 0;
}
__global__ __launch_bounds__(256) void decode_kernel(const unsigned int* __restrict__ ei32) {
    int i = blockIdx.x * blockDim.x + threadIdx.x;
    if (i >= EE) return;
    if (g_is64) {
        g_row[i] = (int)ei32[2 * (size_t)i];
        g_col[i] = (int)ei32[2 * ((size_t)EE + i)];
    } else {
        g_row[i] = (int)ei32[i];
        g_col[i] = (int)ei32[(size_t)EE + i];
    }
}

// ---------------- init: ssum=0, acc=0 -------------------------------------------
__global__ void init_kernel() {
    int i = blockIdx.x * blockDim.x + threadIdx.x;
    if (i < NN * HH) g_ssum[i] = 0.0f;
    if (i < NN * DD) g_acc[i] = 0.0f;
}

// ---------------- weight prep: transpose + hi/lo split ---------------------------
__global__ __launch_bounds__(256) void prep_kernel(
    const float* __restrict__ Wq, const float* __restrict__ Wk,
    const float* __restrict__ Wv, const float* __restrict__ Wo)
{
    int m = blockIdx.y;
    const float* src = (m == 0) ? Wq : (m == 1) ? Wk : (m == 2) ? Wv : Wo;
    int idx = blockIdx.x * 256 + threadIdx.x;   // 0..16383
    int n = idx >> 7, k = idx & 127;
    float v = src[k * 128 + n];
    __nv_bfloat16 h = __float2bfloat16_rn(v);
    __nv_bfloat16 l = __float2bfloat16_rn(v - __bfloat162float(h));
    g_B[m][0][n * 128 + k] = h;
    g_B[m][1][n * 128 + k] = l;
}

// ---------------- tensor-core GEMM (split bf16, 3-product fp32 restore) ---------
// C[M,128] = A[M,128] @ W + bias.  B = g_B[mat] (N x K hi/lo planes).
// If NORM: A rows pre-scaled per-head by 1/(ssum[row][head]+1e-8).
// OUT_HALF: store results as __half (for edge phase), else fp32.
#define PS      (128 * 136)          // plane elems
#define PSB     (PS * 2)             // plane bytes
#define SB_OFF  (2 * PSB)            // sB byte offset
#define SMEM_GEMM (4 * PSB)          // 139264 bytes

template <bool NORM, bool OUT_HALF>
__device__ __forceinline__ void gemm_mma_body(
    const float* __restrict__ A, const __nv_bfloat16* __restrict__ Bsrc,
    const float* __restrict__ bias, void* __restrict__ Cv, int M)
{
    extern __shared__ __nv_bfloat16 smem[];
    const uint32_t sb = smem_u32(smem);
    const int tid = threadIdx.x;
    const int lane = tid & 31;
    const int wid = tid >> 5;
    const int warp_m = wid >> 1;          // 0..3  -> 32 rows
    const int warp_n = wid & 1;           // 0..1  -> 64 cols
    const int block_row = blockIdx.x * 128;

    // ---- load B planes (hi then lo) into sB with stride 136 ----
    {
        const uint32_t* src = (const uint32_t*)Bsrc;       // 2 planes x 8192 u32
        uint32_t* dst = (uint32_t*)(smem + 2 * PS);
#pragma unroll
        for (int p = 0; p < 2; p++) {
#pragma unroll 8
            for (int i = tid; i < 8192; i += 256) {
                int row = i >> 6, colw = i & 63;
                dst[p * (PS / 2) + row * 68 + colw] = src[p * 8192 + i];
            }
        }
    }

    // ---- convert A tile fp32 -> hi/lo bf16 planes (stride 136) ----
    {
        int r = tid >> 1;                       // 0..127
        int half = tid & 1;                     // 64-col half
        int gr = block_row + r;
        uint32_t* hi = (uint32_t*)smem + (r * 136 + half * 64) / 2;
        uint32_t* lo = hi + PS / 2;
        if (gr < M) {
            const float4* Arow = (const float4*)(A + (size_t)gr * 128 + half * 64);
            float sc[4];
            if (NORM) {
#pragma unroll
                for (int h = 0; h < 4; h++)
                    sc[h] = 1.0f / (g_ssum[gr * 8 + half * 4 + h] + 1e-8f);
            }
#pragma unroll
            for (int i = 0; i < 16; i++) {
                float4 a = Arow[i];
                if (NORM) { float s = sc[i >> 2]; a.x *= s; a.y *= s; a.z *= s; a.w *= s; }
                hi[2 * i]     = pack_bf16(bf16_round(a.x), bf16_round(a.y));
                hi[2 * i + 1] = pack_bf16(bf16_round(a.z), bf16_round(a.w));
                lo[2 * i]     = pack_bf16(a.x - bf16_round(a.x), a.y - bf16_round(a.y));
                lo[2 * i + 1] = pack_bf16(a.z - bf16_round(a.z), a.w - bf16_round(a.w));
            }
        } else {
#pragma unroll
            for (int i = 0; i < 32; i++) { hi[i] = 0u; lo[i] = 0u; }
        }
    }
    __syncthreads();

    // ---- fragment addresses (bytes), stride 136 bf16 = 272 B ----
    uint32_t aAddr[2];
#pragma unroll
    for (int mt = 0; mt < 2; mt++)
        aAddr[mt] = sb + ((warp_m * 32 + mt * 16 + (lane & 15)) * 136 +
                          ((lane >> 4) << 3)) * 2;
    uint32_t bAddr[4];
#pragma unroll
    for (int g = 0; g < 4; g++)
        bAddr[g] = sb + SB_OFF +
                   ((warp_n * 64 + g * 16 + ((lane >> 4) << 3) + (lane & 7)) * 136 +
                    (((lane >> 3) & 1) << 3)) * 2;

    float c[2][8][4];
#pragma unroll
    for (int mt = 0; mt < 2; mt++)
#pragma unroll
        for (int nt = 0; nt < 8; nt++)
#pragma unroll
            for (int j = 0; j < 4; j++) c[mt][nt][j] = 0.0f;

    // ---- main loop: 3 passes (Ah*Bh, Ah*Bl, Al*Bh) x 8 k16-steps ----
#pragma unroll
    for (int pass = 0; pass < 3; pass++) {
        const uint32_t aOff = (pass == 2) ? PSB : 0u;
        const uint32_t bOff = (pass == 1) ? PSB : 0u;
#pragma unroll
        for (int k = 0; k < 8; k++) {
            const uint32_t kb = (uint32_t)k * 32;   // 16 bf16 = 32 B
            uint32_t a[2][4];
#pragma unroll
            for (int mt = 0; mt < 2; mt++)
                ldmatrix_x4(a[mt][0], a[mt][1], a[mt][2], a[mt][3],
                            aAddr[mt] + aOff + kb);
            uint32_t b[8][2];
#pragma unroll
            for (int g = 0; g < 4; g++) {
                uint32_t r0, r1, r2, r3;
                ldmatrix_x4(r0, r1, r2, r3, bAddr[g] + bOff + kb);
                b[2 * g][0] = r0; b[2 * g][1] = r1;
                b[2 * g + 1][0] = r2; b[2 * g + 1][1] = r3;
            }
#pragma unroll
            for (int mt = 0; mt < 2; mt++)
#pragma unroll
                for (int nt = 0; nt < 8; nt++)
                    mma_bf16(c[mt][nt], a[mt], b[nt]);
        }
    }

    // ---- epilogue: +bias, store (fp32 or fp16) ----
#pragma unroll
    for (int mt = 0; mt < 2; mt++) {
        int m0 = block_row + warp_m * 32 + mt * 16 + (lane >> 2);
#pragma unroll
        for (int nt = 0; nt < 8; nt++) {
            int n0 = warp_n * 64 + nt * 8 + (lane & 3) * 2;
            float bx = __ldg(bias + n0), by = __ldg(bias + n0 + 1);
            if (OUT_HALF) {
                __half* C = (__half*)Cv;
                if (m0 < M)
                    *(__half2*)(C + (size_t)m0 * 128 + n0) =
                        __floats2half2_rn(c[mt][nt][0] + bx, c[mt][nt][1] + by);
                if (m0 + 8 < M)
                    *(__half2*)(C + (size_t)(m0 + 8) * 128 + n0) =
                        __floats2half2_rn(c[mt][nt][2] + bx, c[mt][nt][3] + by);
            } else {
                float* C = (float*)Cv;
                if (m0 < M)
                    *(float2*)(C + (size_t)m0 * 128 + n0) =
                        make_float2(c[mt][nt][0] + bx, c[mt][nt][1] + by);
                if (m0 + 8 < M)
                    *(float2*)(C + (size_t)(m0 + 8) * 128 + n0) =
                        make_float2(c[mt][nt][2] + bx, c[mt][nt][3] + by);
            }
        }
    }
}

// QKV: blockIdx.y = mat; outputs fp16
__global__ __launch_bounds__(256, 1) void gemm_qkv_mma(
    const float* __restrict__ x,
    const float* __restrict__ bq, const float* __restrict__ bk,
    const float* __restrict__ bv, int M)
{
    int m = blockIdx.y;
    const float* bias = (m == 0) ? bq : (m == 1) ? bk : bv;
    __half* C = (m == 0) ? g_Qh : (m == 1) ? g_Kh : g_Vh;
    gemm_mma_body<false, true>(x, &g_B[m][0][0], bias, C, M);
}

// output projection with fused softmax normalization; fp32 out
__global__ __launch_bounds__(256, 1) void gemm_out_mma(
    const float* __restrict__ bo, float* __restrict__ out, int M)
{
    gemm_mma_body<true, false>(g_acc, &g_B[3][0][0], bo, out, M);
}

// ---------------- fused edge pass (fp16 gathers, fp32 math + scatter) -----------
__global__ __launch_bounds__(256) void edge_kernel(const float* __restrict__ ea)
{
    int e = (blockIdx.x * blockDim.x + threadIdx.x) >> 5;
    if (e >= EE) return;
    int lane = threadIdx.x & 31;
    int row = g_row[e];
    int col = g_col[e];

    // lane loads 4 halves (8B) of Q[row] and K[col]
    uint2 qw = ((const uint2*)(g_Qh + (size_t)row * 128))[lane];
    uint2 kw = ((const uint2*)(g_Kh + (size_t)col * 128))[lane];
    float2 qa = __half22float2(*(__half2*)&qw.x);
    float2 qb = __half22float2(*(__half2*)&qw.y);
    float2 ka = __half22float2(*(__half2*)&kw.x);
    float2 kb = __half22float2(*(__half2*)&kw.y);
    float p = qa.x * ka.x + qa.y * ka.y + qb.x * kb.x + qb.y * kb.y;
    p += __shfl_xor_sync(0xFFFFFFFFu, p, 1);
    p += __shfl_xor_sync(0xFFFFFFFFu, p, 2);   // all 4 lanes of head h hold dot_h

    float s = __expf(fmaf(p, INV_SCALE, ea[e]));

    if ((lane & 3) == 0) atomicAdd(&g_ssum[row * HH + (lane >> 2)], s);

    uint2 vw = ((const uint2*)(g_Vh + (size_t)col * 128))[lane];
    float2 va = __half22float2(*(__half2*)&vw.x);
    float2 vb = __half22float2(*(__half2*)&vw.y);
    redAddV4(g_acc + (size_t)row * 128 + lane * 4,
             s * va.x, s * va.y, s * vb.x, s * vb.y);
}

// ---------------- launch ----------------------------------------------------------
extern "C" void kernel_launch(void* const* d_in, const int* in_sizes, int n_in,
                              void* d_out, int out_size)
{
    const float*        x   = (const float*)d_in[0];
    const unsigned int* ei  = (const unsigned int*)d_in[1];
    const float*        ea  = (const float*)d_in[2];
    const float*        Wq  = (const float*)d_in[3];
    const float*        bq  = (const float*)d_in[4];
    const float*        Wk  = (const float*)d_in[5];
    const float*        bk  = (const float*)d_in[6];
    const float*        Wv  = (const float*)d_in[7];
    const float*        bv  = (const float*)d_in[8];
    const float*        Wo  = (const float*)d_in[9];
    const float*        bo  = (const float*)d_in[10];
    float*              out = (float*)d_out;

    cudaFuncSetAttribute(gemm_qkv_mma, cudaFuncAttributeMaxDynamicSharedMemorySize, SMEM_GEMM);
    cudaFuncSetAttribute(gemm_out_mma, cudaFuncAttributeMaxDynamicSharedMemorySize, SMEM_GEMM);

    // edge_index dtype detection + decode
    detect_kernel<<<1, 1>>>(ei);
    decode_kernel<<<(EE + 255) / 256, 256>>>(ei);

    // init ssum / acc
    init_kernel<<<(NN * DD + 255) / 256, 256>>>();

    // weight prep (transpose + hi/lo split)
    {
        dim3 grid(64, 4);
        prep_kernel<<<grid, 256>>>(Wq, Wk, Wv, Wo);
    }

    // fused Q,K,V projections on tensor cores (fp16 outputs)
    {
        dim3 grid((NN + 127) / 128, 3);
        gemm_qkv_mma<<<grid, 256, SMEM_GEMM>>>(x, bq, bk, bv, NN);
    }

    // fused scores + exp + segment-sum + scatter
    edge_kernel<<<(EE + 7) / 8, 256>>>(ea);

    // output projection (normalization fused) on tensor cores
    gemm_out_mma<<<(NN + 127) / 128, 256, SMEM_GEMM>>>(bo, out, NN);
}

// round 8
// speedup vs baseline: 2.8077x; 1.2744x over previous
#include <cuda_runtime.h>
#include <cuda_bf16.h>
#include <cuda_fp16.h>
#include <math.h>
#include <stdint.h>

#define NN 50000
#define EE 600000
#define DD 128
#define HH 8
#define INV_SCALE 0.25f   // 1/sqrt(16)

// ---------------- scratch (static device allocations; no cudaMalloc) ----------
__device__ __half g_Qh[(size_t)NN * DD];
__device__ __half g_Kh[(size_t)NN * DD];
__device__ __half g_Vh[(size_t)NN * DD];
__device__ float  g_ssum[(size_t)NN * HH];
__device__ float  g_acc[(size_t)NN * DD];
__device__ int    g_row[EE];
__device__ int    g_col[EE];
__device__ int    g_is64;
// pre-transposed weights fp16, stored N x K row-major: g_B[mat][n*128+k] = W[k][n]
__device__ __align__(16) __half g_B[4][128 * 128];

// ---------------- helpers -------------------------------------------------------
__device__ __forceinline__ uint32_t smem_u32(const void* p) {
    uint32_t a;
    asm("{ .reg .u64 t; cvta.to.shared.u64 t, %1; cvt.u32.u64 %0, t; }" : "=r"(a) : "l"(p));
    return a;
}
__device__ __forceinline__ void redAddV4(float* addr, float a, float b, float c, float d) {
    asm volatile("red.global.add.v4.f32 [%0], {%1, %2, %3, %4};"
                 :: "l"(addr), "f"(a), "f"(b), "f"(c), "f"(d) : "memory");
}
__device__ __forceinline__ uint32_t pack_f16(float x, float y) {
    __half2 t = __floats2half2_rn(x, y);
    return *(uint32_t*)&t;
}
__device__ __forceinline__ void ldmatrix_x4(uint32_t& r0, uint32_t& r1,
                                            uint32_t& r2, uint32_t& r3, uint32_t addr) {
    asm volatile("ldmatrix.sync.aligned.m8n8.x4.shared.b16 {%0,%1,%2,%3}, [%4];"
                 : "=r"(r0), "=r"(r1), "=r"(r2), "=r"(r3) : "r"(addr));
}
__device__ __forceinline__ void mma_f16(float* c, const uint32_t* a, const uint32_t* b) {
    asm volatile(
        "mma.sync.aligned.m16n8k16.row.col.f32.f16.f16.f32 "
        "{%0,%1,%2,%3}, {%4,%5,%6,%7}, {%8,%9}, {%0,%1,%2,%3};"
        : "+f"(c[0]), "+f"(c[1]), "+f"(c[2]), "+f"(c[3])
        : "r"(a[0]), "r"(a[1]), "r"(a[2]), "r"(a[3]), "r"(b[0]), "r"(b[1]));
}

// ---------------- edge_index dtype detection + decode ---------------------------
__global__ void detect_kernel(const unsigned int* __restrict__ ei32) {
    unsigned int acc = 0;
#pragma unroll
    for (int i = 0; i < 64; i++) acc |= ei32[2 * i + 1];
    g_is64 = (acc == 0) ? 1 : 0;
}
__global__ __launch_bounds__(256) void decode_kernel(const unsigned int* __restrict__ ei32) {
    int i = blockIdx.x * blockDim.x + threadIdx.x;
    if (i >= EE) return;
    if (g_is64) {
        g_row[i] = (int)ei32[2 * (size_t)i];
        g_col[i] = (int)ei32[2 * ((size_t)EE + i)];
    } else {
        g_row[i] = (int)ei32[i];
        g_col[i] = (int)ei32[(size_t)EE + i];
    }
}

// ---------------- init: ssum=0, acc=0 -------------------------------------------
__global__ void init_kernel() {
    int i = blockIdx.x * blockDim.x + threadIdx.x;
    if (i < NN * HH) g_ssum[i] = 0.0f;
    if (i < NN * DD) g_acc[i] = 0.0f;
}

// ---------------- weight prep: transpose -> fp16 ---------------------------------
__global__ __launch_bounds__(256) void prep_kernel(
    const float* __restrict__ Wq, const float* __restrict__ Wk,
    const float* __restrict__ Wv, const float* __restrict__ Wo)
{
    int m = blockIdx.y;
    const float* src = (m == 0) ? Wq : (m == 1) ? Wk : (m == 2) ? Wv : Wo;
    int idx = blockIdx.x * 256 + threadIdx.x;   // 0..16383
    int n = idx >> 7, k = idx & 127;
    g_B[m][n * 128 + k] = __float2half_rn(src[k * 128 + n]);
}

// ---------------- tensor-core GEMM (single-pass fp16, fp32 accumulate) ----------
// C[M,128] = A[M,128] @ W + bias.  B = g_B[mat] (N x K fp16).
// If NORM: A rows pre-scaled per-head by 1/(ssum[row][head]+1e-8).
// OUT_HALF: store results as __half, else fp32.
#define PS      (128 * 136)          // plane elems (bf16/fp16)
#define SMEM_GEMM (2 * PS * 2)       // 69632 bytes: sA + sB

template <bool NORM, bool OUT_HALF>
__device__ __forceinline__ void gemm_mma_body(
    const float* __restrict__ A, const __half* __restrict__ Bsrc,
    const float* __restrict__ bias, void* __restrict__ Cv, int M)
{
    extern __shared__ __half smem[];
    const uint32_t sb = smem_u32(smem);
    const int tid = threadIdx.x;
    const int lane = tid & 31;
    const int wid = tid >> 5;
    const int warp_m = wid >> 1;          // 0..3  -> 32 rows
    const int warp_n = wid & 1;           // 0..1  -> 64 cols
    const int block_row = blockIdx.x * 128;

    // ---- load B plane into sB with stride 136 ----
    {
        const uint32_t* src = (const uint32_t*)Bsrc;       // 8192 u32
        uint32_t* dst = (uint32_t*)(smem + PS);
#pragma unroll 8
        for (int i = tid; i < 8192; i += 256) {
            int row = i >> 6, colw = i & 63;
            dst[row * 68 + colw] = src[i];
        }
    }

    // ---- convert A tile fp32 -> fp16 plane (stride 136) ----
    {
        int r = tid >> 1;                       // 0..127
        int half = tid & 1;                     // 64-col half
        int gr = block_row + r;
        uint32_t* dst = (uint32_t*)smem + (r * 136 + half * 64) / 2;
        if (gr < M) {
            const float4* Arow = (const float4*)(A + (size_t)gr * 128 + half * 64);
            float sc[4];
            if (NORM) {
#pragma unroll
                for (int h = 0; h < 4; h++)
                    sc[h] = 1.0f / (g_ssum[gr * 8 + half * 4 + h] + 1e-8f);
            }
#pragma unroll
            for (int i = 0; i < 16; i++) {
                float4 a = Arow[i];
                if (NORM) { float s = sc[i >> 2]; a.x *= s; a.y *= s; a.z *= s; a.w *= s; }
                dst[2 * i]     = pack_f16(a.x, a.y);
                dst[2 * i + 1] = pack_f16(a.z, a.w);
            }
        } else {
#pragma unroll
            for (int i = 0; i < 32; i++) dst[i] = 0u;
        }
    }
    __syncthreads();

    // ---- fragment addresses (bytes), stride 136 fp16 = 272 B ----
    uint32_t aAddr[2];
#pragma unroll
    for (int mt = 0; mt < 2; mt++)
        aAddr[mt] = sb + ((warp_m * 32 + mt * 16 + (lane & 15)) * 136 +
                          ((lane >> 4) << 3)) * 2;
    uint32_t bAddr[4];
#pragma unroll
    for (int g = 0; g < 4; g++)
        bAddr[g] = sb + PS * 2 +
                   ((warp_n * 64 + g * 16 + ((lane >> 4) << 3) + (lane & 7)) * 136 +
                    (((lane >> 3) & 1) << 3)) * 2;

    float c[2][8][4];
#pragma unroll
    for (int mt = 0; mt < 2; mt++)
#pragma unroll
        for (int nt = 0; nt < 8; nt++)
#pragma unroll
            for (int j = 0; j < 4; j++) c[mt][nt][j] = 0.0f;

    // ---- main loop: 8 k16-steps, single pass ----
#pragma unroll
    for (int k = 0; k < 8; k++) {
        const uint32_t kb = (uint32_t)k * 32;   // 16 fp16 = 32 B
        uint32_t a[2][4];
#pragma unroll
        for (int mt = 0; mt < 2; mt++)
            ldmatrix_x4(a[mt][0], a[mt][1], a[mt][2], a[mt][3], aAddr[mt] + kb);
        uint32_t b[8][2];
#pragma unroll
        for (int g = 0; g < 4; g++) {
            uint32_t r0, r1, r2, r3;
            ldmatrix_x4(r0, r1, r2, r3, bAddr[g] + kb);
            b[2 * g][0] = r0; b[2 * g][1] = r1;
            b[2 * g + 1][0] = r2; b[2 * g + 1][1] = r3;
        }
#pragma unroll
        for (int mt = 0; mt < 2; mt++)
#pragma unroll
            for (int nt = 0; nt < 8; nt++)
                mma_f16(c[mt][nt], a[mt], b[nt]);
    }

    // ---- epilogue: +bias, store (fp32 or fp16) ----
#pragma unroll
    for (int mt = 0; mt < 2; mt++) {
        int m0 = block_row + warp_m * 32 + mt * 16 + (lane >> 2);
#pragma unroll
        for (int nt = 0; nt < 8; nt++) {
            int n0 = warp_n * 64 + nt * 8 + (lane & 3) * 2;
            float bx = __ldg(bias + n0), by = __ldg(bias + n0 + 1);
            if (OUT_HALF) {
                __half* C = (__half*)Cv;
                if (m0 < M)
                    *(__half2*)(C + (size_t)m0 * 128 + n0) =
                        __floats2half2_rn(c[mt][nt][0] + bx, c[mt][nt][1] + by);
                if (m0 + 8 < M)
                    *(__half2*)(C + (size_t)(m0 + 8) * 128 + n0) =
                        __floats2half2_rn(c[mt][nt][2] + bx, c[mt][nt][3] + by);
            } else {
                float* C = (float*)Cv;
                if (m0 < M)
                    *(float2*)(C + (size_t)m0 * 128 + n0) =
                        make_float2(c[mt][nt][0] + bx, c[mt][nt][1] + by);
                if (m0 + 8 < M)
                    *(float2*)(C + (size_t)(m0 + 8) * 128 + n0) =
                        make_float2(c[mt][nt][2] + bx, c[mt][nt][3] + by);
            }
        }
    }
}

// QKV: blockIdx.y = mat; outputs fp16
__global__ __launch_bounds__(256) void gemm_qkv_mma(
    const float* __restrict__ x,
    const float* __restrict__ bq, const float* __restrict__ bk,
    const float* __restrict__ bv, int M)
{
    int m = blockIdx.y;
    const float* bias = (m == 0) ? bq : (m == 1) ? bk : bv;
    __half* C = (m == 0) ? g_Qh : (m == 1) ? g_Kh : g_Vh;
    gemm_mma_body<false, true>(x, &g_B[m][0], bias, C, M);
}

// output projection with fused softmax normalization; fp32 out
__global__ __launch_bounds__(256) void gemm_out_mma(
    const float* __restrict__ bo, float* __restrict__ out, int M)
{
    gemm_mma_body<true, false>(g_acc, &g_B[3][0], bo, out, M);
}

// ---------------- fused edge pass (fp16 gathers, fp32 math + scatter) -----------
__global__ __launch_bounds__(256) void edge_kernel(const float* __restrict__ ea)
{
    int e = (blockIdx.x * blockDim.x + threadIdx.x) >> 5;
    if (e >= EE) return;
    int lane = threadIdx.x & 31;
    int row = g_row[e];
    int col = g_col[e];

    uint2 qw = ((const uint2*)(g_Qh + (size_t)row * 128))[lane];
    uint2 kw = ((const uint2*)(g_Kh + (size_t)col * 128))[lane];
    float2 qa = __half22float2(*(__half2*)&qw.x);
    float2 qb = __half22float2(*(__half2*)&qw.y);
    float2 ka = __half22float2(*(__half2*)&kw.x);
    float2 kb = __half22float2(*(__half2*)&kw.y);
    float p = qa.x * ka.x + qa.y * ka.y + qb.x * kb.x + qb.y * kb.y;
    p += __shfl_xor_sync(0xFFFFFFFFu, p, 1);
    p += __shfl_xor_sync(0xFFFFFFFFu, p, 2);   // all 4 lanes of head h hold dot_h

    float s = __expf(fmaf(p, INV_SCALE, ea[e]));

    if ((lane & 3) == 0) atomicAdd(&g_ssum[row * HH + (lane >> 2)], s);

    uint2 vw = ((const uint2*)(g_Vh + (size_t)col * 128))[lane];
    float2 va = __half22float2(*(__half2*)&vw.x);
    float2 vb = __half22float2(*(__half2*)&vw.y);
    redAddV4(g_acc + (size_t)row * 128 + lane * 4,
             s * va.x, s * va.y, s * vb.x, s * vb.y);
}

// ---------------- launch ----------------------------------------------------------
extern "C" void kernel_launch(void* const* d_in, const int* in_sizes, int n_in,
                              void* d_out, int out_size)
{
    const float*        x   = (const float*)d_in[0];
    const unsigned int* ei  = (const unsigned int*)d_in[1];
    const float*        ea  = (const float*)d_in[2];
    const float*        Wq  = (const float*)d_in[3];
    const float*        bq  = (const float*)d_in[4];
    const float*        Wk  = (const float*)d_in[5];
    const float*        bk  = (const float*)d_in[6];
    const float*        Wv  = (const float*)d_in[7];
    const float*        bv  = (const float*)d_in[8];
    const float*        Wo  = (const float*)d_in[9];
    const float*        bo  = (const float*)d_in[10];
    float*              out = (float*)d_out;

    cudaFuncSetAttribute(gemm_qkv_mma, cudaFuncAttributeMaxDynamicSharedMemorySize, SMEM_GEMM);
    cudaFuncSetAttribute(gemm_out_mma, cudaFuncAttributeMaxDynamicSharedMemorySize, SMEM_GEMM);

    // edge_index dtype detection + decode
    detect_kernel<<<1, 1>>>(ei);
    decode_kernel<<<(EE + 255) / 256, 256>>>(ei);

    // init ssum / acc
    init_kernel<<<(NN * DD + 255) / 256, 256>>>();

    // weight prep (transpose -> fp16)
    {
        dim3 grid(64, 4);
        prep_kernel<<<grid, 256>>>(Wq, Wk, Wv, Wo);
    }

    // fused Q,K,V projections on tensor cores (fp16 outputs)
    {
        dim3 grid((NN + 127) / 128, 3);
        gemm_qkv_mma<<<grid, 256, SMEM_GEMM>>>(x, bq, bk, bv, NN);
    }

    // fused scores + exp + segment-sum + scatter
    edge_kernel<<<(EE + 7) / 8, 256>>>(ea);

    // output projection (normalization fused) on tensor cores
    gemm_out_mma<<<(NN + 127) / 128, 256, SMEM_GEMM>>>(bo, out, NN);
}

// round 9
// speedup vs baseline: 3.9325x; 1.4006x over previous
#include <cuda_runtime.h>
#include <cuda_fp16.h>
#include <math.h>
#include <stdint.h>

#define NN 50000
#define EE 600000
#define DD 128
#define HH 8
#define INV_SCALE 0.25f   // 1/sqrt(16)
#define NPAD 50176        // 196 * 256
#define NB 196

// ---------------- scratch (static device allocations; no cudaMalloc) ----------
__device__ __half g_Qh[(size_t)NN * DD];
__device__ __half g_Kh[(size_t)NN * DD];
__device__ __half g_Vh[(size_t)NN * DD];
__device__ float  g_acc[(size_t)NN * DD];
__device__ int    g_cnt[NPAD];
__device__ int    g_cur[NPAD];
__device__ int    g_off[NPAD];
__device__ int    g_bsum[256];
__device__ uint2  g_sedge[EE];    // {col, bits(edge_attr)} sorted by row
__device__ int    g_is64;
// pre-transposed weights fp16, stored N x K row-major: g_B[mat][n*128+k] = W[k][n]
__device__ __align__(16) __half g_B[4][128 * 128];

// ---------------- helpers -------------------------------------------------------
__device__ __forceinline__ uint32_t smem_u32(const void* p) {
    uint32_t a;
    asm("{ .reg .u64 t; cvta.to.shared.u64 t, %1; cvt.u32.u64 %0, t; }" : "=r"(a) : "l"(p));
    return a;
}
__device__ __forceinline__ uint32_t pack_f16(float x, float y) {
    __half2 t = __floats2half2_rn(x, y);
    return *(uint32_t*)&t;
}
__device__ __forceinline__ void ldmatrix_x4(uint32_t& r0, uint32_t& r1,
                                            uint32_t& r2, uint32_t& r3, uint32_t addr) {
    asm volatile("ldmatrix.sync.aligned.m8n8.x4.shared.b16 {%0,%1,%2,%3}, [%4];"
                 : "=r"(r0), "=r"(r1), "=r"(r2), "=r"(r3) : "r"(addr));
}
__device__ __forceinline__ void mma_f16(float* c, const uint32_t* a, const uint32_t* b) {
    asm volatile(
        "mma.sync.aligned.m16n8k16.row.col.f32.f16.f16.f32 "
        "{%0,%1,%2,%3}, {%4,%5,%6,%7}, {%8,%9}, {%0,%1,%2,%3};"
        : "+f"(c[0]), "+f"(c[1]), "+f"(c[2]), "+f"(c[3])
        : "r"(a[0]), "r"(a[1]), "r"(a[2]), "r"(a[3]), "r"(b[0]), "r"(b[1]));
}
__device__ __forceinline__ int decode_row(const unsigned int* ei32, int i) {
    return g_is64 ? (int)ei32[2 * (size_t)i] : (int)ei32[i];
}
__device__ __forceinline__ int decode_col(const unsigned int* ei32, int i) {
    return g_is64 ? (int)ei32[2 * ((size_t)EE + i)] : (int)ei32[(size_t)EE + i];
}

// ---------------- edge_index dtype detection -------------------------------------
__global__ void detect_kernel(const unsigned int* __restrict__ ei32) {
    unsigned int acc = 0;
#pragma unroll
    for (int i = 0; i < 64; i++) acc |= ei32[2 * i + 1];
    g_is64 = (acc == 0) ? 1 : 0;
}

// ---------------- counting sort: zero -> hist -> scan -> permute ----------------
__global__ __launch_bounds__(256) void zero_kernel() {
    int i = blockIdx.x * blockDim.x + threadIdx.x;
    if (i < NPAD) { g_cnt[i] = 0; g_cur[i] = 0; }
}
__global__ __launch_bounds__(256) void hist_kernel(const unsigned int* __restrict__ ei32) {
    int i = blockIdx.x * blockDim.x + threadIdx.x;
    if (i >= EE) return;
    atomicAdd(&g_cnt[decode_row(ei32, i)], 1);
}
__global__ __launch_bounds__(256) void scan1_kernel() {
    __shared__ int s[256];
    int tid = threadIdx.x;
    int i = blockIdx.x * 256 + tid;
    int v = g_cnt[i];
    s[tid] = v;
    __syncthreads();
#pragma unroll
    for (int d = 1; d < 256; d <<= 1) {
        int t = (tid >= d) ? s[tid - d] : 0;
        __syncthreads();
        s[tid] += t;
        __syncthreads();
    }
    g_off[i] = s[tid] - v;                 // exclusive within block
    if (tid == 255) g_bsum[blockIdx.x] = s[255];
}
__global__ __launch_bounds__(256) void scan2_kernel() {
    __shared__ int s[256];
    int tid = threadIdx.x;
    int v = (tid < NB) ? g_bsum[tid] : 0;
    s[tid] = v;
    __syncthreads();
#pragma unroll
    for (int d = 1; d < 256; d <<= 1) {
        int t = (tid >= d) ? s[tid - d] : 0;
        __syncthreads();
        s[tid] += t;
        __syncthreads();
    }
    g_bsum[tid] = s[tid] - v;              // exclusive block offsets
}
__global__ __launch_bounds__(256) void permute_kernel(
    const unsigned int* __restrict__ ei32, const float* __restrict__ ea)
{
    int i = blockIdx.x * blockDim.x + threadIdx.x;
    if (i >= EE) return;
    int row = decode_row(ei32, i);
    int col = decode_col(ei32, i);
    int pos = g_off[row] + g_bsum[row >> 8] + atomicAdd(&g_cur[row], 1);
    g_sedge[pos] = make_uint2((unsigned)col, __float_as_uint(ea[i]));
}

// ---------------- weight prep: transpose -> fp16 ---------------------------------
__global__ __launch_bounds__(256) void prep_kernel(
    const float* __restrict__ Wq, const float* __restrict__ Wk,
    const float* __restrict__ Wv, const float* __restrict__ Wo)
{
    int m = blockIdx.y;
    const float* src = (m == 0) ? Wq : (m == 1) ? Wk : (m == 2) ? Wv : Wo;
    int idx = blockIdx.x * 256 + threadIdx.x;   // 0..16383
    int n = idx >> 7, k = idx & 127;
    g_B[m][n * 128 + k] = __float2half_rn(src[k * 128 + n]);
}

// ---------------- tensor-core GEMM (single-pass fp16, fp32 accumulate) ----------
#define PS      (128 * 136)
#define SMEM_GEMM (2 * PS * 2)       // 69632 bytes: sA + sB

template <bool OUT_HALF>
__device__ __forceinline__ void gemm_mma_body(
    const float* __restrict__ A, const __half* __restrict__ Bsrc,
    const float* __restrict__ bias, void* __restrict__ Cv, int M)
{
    extern __shared__ __half smem[];
    const uint32_t sb = smem_u32(smem);
    const int tid = threadIdx.x;
    const int lane = tid & 31;
    const int wid = tid >> 5;
    const int warp_m = wid >> 1;
    const int warp_n = wid & 1;
    const int block_row = blockIdx.x * 128;

    // ---- load B plane into sB with stride 136 ----
    {
        const uint32_t* src = (const uint32_t*)Bsrc;
        uint32_t* dst = (uint32_t*)(smem + PS);
#pragma unroll 8
        for (int i = tid; i < 8192; i += 256) {
            int row = i >> 6, colw = i & 63;
            dst[row * 68 + colw] = src[i];
        }
    }

    // ---- convert A tile fp32 -> fp16 plane (stride 136) ----
    {
        int r = tid >> 1;
        int half = tid & 1;
        int gr = block_row + r;
        uint32_t* dst = (uint32_t*)smem + (r * 136 + half * 64) / 2;
        if (gr < M) {
            const float4* Arow = (const float4*)(A + (size_t)gr * 128 + half * 64);
#pragma unroll
            for (int i = 0; i < 16; i++) {
                float4 a = Arow[i];
                dst[2 * i]     = pack_f16(a.x, a.y);
                dst[2 * i + 1] = pack_f16(a.z, a.w);
            }
        } else {
#pragma unroll
            for (int i = 0; i < 32; i++) dst[i] = 0u;
        }
    }
    __syncthreads();

    uint32_t aAddr[2];
#pragma unroll
    for (int mt = 0; mt < 2; mt++)
        aAddr[mt] = sb + ((warp_m * 32 + mt * 16 + (lane & 15)) * 136 +
                          ((lane >> 4) << 3)) * 2;
    uint32_t bAddr[4];
#pragma unroll
    for (int g = 0; g < 4; g++)
        bAddr[g] = sb + PS * 2 +
                   ((warp_n * 64 + g * 16 + ((lane >> 4) << 3) + (lane & 7)) * 136 +
                    (((lane >> 3) & 1) << 3)) * 2;

    float c[2][8][4];
#pragma unroll
    for (int mt = 0; mt < 2; mt++)
#pragma unroll
        for (int nt = 0; nt < 8; nt++)
#pragma unroll
            for (int j = 0; j < 4; j++) c[mt][nt][j] = 0.0f;

#pragma unroll
    for (int k = 0; k < 8; k++) {
        const uint32_t kb = (uint32_t)k * 32;
        uint32_t a[2][4];
#pragma unroll
        for (int mt = 0; mt < 2; mt++)
            ldmatrix_x4(a[mt][0], a[mt][1], a[mt][2], a[mt][3], aAddr[mt] + kb);
        uint32_t b[8][2];
#pragma unroll
        for (int g = 0; g < 4; g++) {
            uint32_t r0, r1, r2, r3;
            ldmatrix_x4(r0, r1, r2, r3, bAddr[g] + kb);
            b[2 * g][0] = r0; b[2 * g][1] = r1;
            b[2 * g + 1][0] = r2; b[2 * g + 1][1] = r3;
        }
#pragma unroll
        for (int mt = 0; mt < 2; mt++)
#pragma unroll
            for (int nt = 0; nt < 8; nt++)
                mma_f16(c[mt][nt], a[mt], b[nt]);
    }

#pragma unroll
    for (int mt = 0; mt < 2; mt++) {
        int m0 = block_row + warp_m * 32 + mt * 16 + (lane >> 2);
#pragma unroll
        for (int nt = 0; nt < 8; nt++) {
            int n0 = warp_n * 64 + nt * 8 + (lane & 3) * 2;
            float bx = __ldg(bias + n0), by = __ldg(bias + n0 + 1);
            if (OUT_HALF) {
                __half* C = (__half*)Cv;
                if (m0 < M)
                    *(__half2*)(C + (size_t)m0 * 128 + n0) =
                        __floats2half2_rn(c[mt][nt][0] + bx, c[mt][nt][1] + by);
                if (m0 + 8 < M)
                    *(__half2*)(C + (size_t)(m0 + 8) * 128 + n0) =
                        __floats2half2_rn(c[mt][nt][2] + bx, c[mt][nt][3] + by);
            } else {
                float* C = (float*)Cv;
                if (m0 < M)
                    *(float2*)(C + (size_t)m0 * 128 + n0) =
                        make_float2(c[mt][nt][0] + bx, c[mt][nt][1] + by);
                if (m0 + 8 < M)
                    *(float2*)(C + (size_t)(m0 + 8) * 128 + n0) =
                        make_float2(c[mt][nt][2] + bx, c[mt][nt][3] + by);
            }
        }
    }
}

__global__ __launch_bounds__(256) void gemm_qkv_mma(
    const float* __restrict__ x,
    const float* __restrict__ bq, const float* __restrict__ bk,
    const float* __restrict__ bv, int M)
{
    int m = blockIdx.y;
    const float* bias = (m == 0) ? bq : (m == 1) ? bk : bv;
    __half* C = (m == 0) ? g_Qh : (m == 1) ? g_Kh : g_Vh;
    gemm_mma_body<true>(x, &g_B[m][0], bias, C, M);
}

__global__ __launch_bounds__(256) void gemm_out_mma(
    const float* __restrict__ bo, float* __restrict__ out, int M)
{
    gemm_mma_body<false>(g_acc, &g_B[3][0], bo, out, M);
}

// ---------------- node-centric aggregation (gather-side reduction) --------------
// One warp per node: Q row in registers; loop over sorted incident edges,
// gather K/V, softmax-accumulate in registers, normalized single store.
__global__ __launch_bounds__(256) void aggregate_kernel()
{
    int n = (blockIdx.x * blockDim.x + threadIdx.x) >> 5;
    if (n >= NN) return;
    int lane = threadIdx.x & 31;

    int base = g_off[n] + g_bsum[n >> 8];
    int deg  = g_cnt[n];

    uint2 qw = ((const uint2*)(g_Qh + (size_t)n * 128))[lane];
    float2 qa = __half22float2(*(__half2*)&qw.x);
    float2 qb = __half22float2(*(__half2*)&qw.y);

    float a0 = 0.f, a1 = 0.f, a2 = 0.f, a3 = 0.f;
    float ssum = 0.f;

    if (deg > 0) {
        uint2 rec = g_sedge[base];
        for (int i = 0; i < deg; i++) {
            int col = (int)rec.x;
            float eav = __uint_as_float(rec.y);
            if (i + 1 < deg) rec = g_sedge[base + i + 1];   // prefetch next record

            uint2 kw = ((const uint2*)(g_Kh + (size_t)col * 128))[lane];
            uint2 vw = ((const uint2*)(g_Vh + (size_t)col * 128))[lane];

            float2 ka = __half22float2(*(__half2*)&kw.x);
            float2 kb = __half22float2(*(__half2*)&kw.y);
            float p = qa.x * ka.x + qa.y * ka.y + qb.x * kb.x + qb.y * kb.y;
            p += __shfl_xor_sync(0xFFFFFFFFu, p, 1);
            p += __shfl_xor_sync(0xFFFFFFFFu, p, 2);   // head dot on all 4 lanes

            float s = __expf(fmaf(p, INV_SCALE, eav));
            ssum += s;

            float2 va = __half22float2(*(__half2*)&vw.x);
            float2 vb = __half22float2(*(__half2*)&vw.y);
            a0 = fmaf(s, va.x, a0);
            a1 = fmaf(s, va.y, a1);
            a2 = fmaf(s, vb.x, a2);
            a3 = fmaf(s, vb.y, a3);
        }
    }

    float inv = 1.0f / (ssum + 1e-8f);
    float4 o = make_float4(a0 * inv, a1 * inv, a2 * inv, a3 * inv);
    *(float4*)(g_acc + (size_t)n * 128 + lane * 4) = o;
}

// ---------------- launch ----------------------------------------------------------
extern "C" void kernel_launch(void* const* d_in, const int* in_sizes, int n_in,
                              void* d_out, int out_size)
{
    const float*        x   = (const float*)d_in[0];
    const unsigned int* ei  = (const unsigned int*)d_in[1];
    const float*        ea  = (const float*)d_in[2];
    const float*        Wq  = (const float*)d_in[3];
    const float*        bq  = (const float*)d_in[4];
    const float*        Wk  = (const float*)d_in[5];
    const float*        bk  = (const float*)d_in[6];
    const float*        Wv  = (const float*)d_in[7];
    const float*        bv  = (const float*)d_in[8];
    const float*        Wo  = (const float*)d_in[9];
    const float*        bo  = (const float*)d_in[10];
    float*              out = (float*)d_out;

    cudaFuncSetAttribute(gemm_qkv_mma, cudaFuncAttributeMaxDynamicSharedMemorySize, SMEM_GEMM);
    cudaFuncSetAttribute(gemm_out_mma, cudaFuncAttributeMaxDynamicSharedMemorySize, SMEM_GEMM);

    // dtype detect + counting sort of edges by destination
    detect_kernel<<<1, 1>>>(ei);
    zero_kernel<<<NPAD / 256, 256>>>();
    hist_kernel<<<(EE + 255) / 256, 256>>>(ei);
    scan1_kernel<<<NB, 256>>>();
    scan2_kernel<<<1, 256>>>();
    permute_kernel<<<(EE + 255) / 256, 256>>>(ei, ea);

    // weight prep (transpose -> fp16)
    {
        dim3 grid(64, 4);
        prep_kernel<<<grid, 256>>>(Wq, Wk, Wv, Wo);
    }

    // fused Q,K,V projections on tensor cores (fp16 outputs)
    {
        dim3 grid((NN + 127) / 128, 3);
        gemm_qkv_mma<<<grid, 256, SMEM_GEMM>>>(x, bq, bk, bv, NN);
    }

    // node-centric softmax aggregation
    aggregate_kernel<<<(NN * 32 + 255) / 256, 256>>>();

    // output projection on tensor cores
    gemm_out_mma<<<(NN + 127) / 128, 256, SMEM_GEMM>>>(bo, out, NN);
}